// round 1
// baseline (speedup 1.0000x reference)
#include <cuda_runtime.h>
#include <cuda_bf16.h>

// Inverse of f(x) = a*x + (1-a)*softplus(x), a = 0.1 + 0.4*sigmoid(raw_alpha).
// Solved by Newton iteration. f' in (a,1), f strictly increasing, quadratic
// convergence from init x0 = (y>0 ? y : y/a). 6 iterations reach fp32-level
// agreement with the 25-iteration reference (worst-case error chain:
// 1.4 -> .36 -> .10 -> 8e-3 -> 5e-5 -> 2e-9).
//
// Per iteration, one exp is shared between softplus and sigmoid:
//   e  = exp(-|x|)
//   sp = log1p(e) + max(x,0)
//   r  = 1/(1+e);  sigma = (x>0) ? r : 1-r
//   fx = a*x + (1-a)*sp ; fp = a + (1-a)*sigma
//   x -= (fx - y) * rcp(fp)
// => 4 MUFU ops/iter (EX2, LG2, RCP, RCP). MUFU-bound kernel.

#define NEWTON_ITERS 6

__device__ __forceinline__ float rcp_approx(float x) {
    float r;
    asm("rcp.approx.ftz.f32 %0, %1;" : "=f"(r) : "f"(x));
    return r;
}

__device__ __forceinline__ float newton_solve(float y, float a, float oma, float inv_a) {
    float x = (y > 0.0f) ? y : y * inv_a;
#pragma unroll
    for (int it = 0; it < NEWTON_ITERS; ++it) {
        float e   = __expf(-fabsf(x));          // MUFU EX2
        float d   = 1.0f + e;
        float l   = __logf(d);                  // MUFU LG2  (= log1p(e), d in [1,2])
        float r   = rcp_approx(d);              // MUFU RCP
        float sp  = l + fmaxf(x, 0.0f);
        float sig = (x > 0.0f) ? r : (1.0f - r);
        float fx  = fmaf(oma, sp, a * x);
        float fp  = fmaf(oma, sig, a);
        float num = fx - y;
        x = fmaf(-num, rcp_approx(fp), x);      // MUFU RCP
    }
    return x;
}

__global__ __launch_bounds__(256)
void inv_leaky_softplus_kernel(const float4* __restrict__ in,
                               const float* __restrict__ raw_alpha,
                               float4* __restrict__ out,
                               int n4, int n_rem,
                               const float* __restrict__ rem_in,
                               float* __restrict__ rem_out) {
    // alpha is a broadcast scalar; one exp per thread is negligible vs 24 MUFU/elem
    float ra    = raw_alpha[0];
    float a     = fmaf(0.4f, rcp_approx(1.0f + __expf(-ra)), 0.1f);
    float oma   = 1.0f - a;
    float inv_a = rcp_approx(a);
    // refine inv_a to full precision (one Newton step on the reciprocal)
    inv_a = inv_a * (2.0f - a * inv_a);

    int i = blockIdx.x * blockDim.x + threadIdx.x;
    if (i < n4) {
        float4 y4 = in[i];
        float4 x4;
        x4.x = newton_solve(y4.x, a, oma, inv_a);
        x4.y = newton_solve(y4.y, a, oma, inv_a);
        x4.z = newton_solve(y4.z, a, oma, inv_a);
        x4.w = newton_solve(y4.w, a, oma, inv_a);
        out[i] = x4;
    }
    // tail elements (n not divisible by 4) — handled by the first n_rem threads
    if (i < n_rem) {
        rem_out[i] = newton_solve(rem_in[i], a, oma, inv_a);
    }
}

extern "C" void kernel_launch(void* const* d_in, const int* in_sizes, int n_in,
                              void* d_out, int out_size) {
    const float* inp   = (const float*)d_in[0];
    const float* alpha = (const float*)d_in[1];
    float*       outp  = (float*)d_out;

    int n     = in_sizes[0];
    int n4    = n >> 2;
    int n_rem = n & 3;
    const float* rem_in  = inp  + (size_t)n4 * 4;
    float*       rem_out = outp + (size_t)n4 * 4;

    int threads = 256;
    int work    = (n4 > n_rem) ? n4 : n_rem;
    int blocks  = (work + threads - 1) / threads;
    if (blocks < 1) blocks = 1;

    inv_leaky_softplus_kernel<<<blocks, threads>>>(
        (const float4*)inp, alpha, (float4*)outp, n4, n_rem, rem_in, rem_out);
}

// round 2
// speedup vs baseline: 1.6819x; 1.6819x over previous
#include <cuda_runtime.h>
#include <cuda_bf16.h>

// Inverse of f(x) = a*x + (1-a)*softplus(x), a = 0.1 + 0.4*sigmoid(raw_alpha).
//
// R2: Halley's method (cubic convergence), 3 iterations, single-RCP algebra.
//   e  = exp(-|x|), d = 1+e, s = (x>0 ? 1 : e)
//   sigma = s/d, f' = (a*d + (1-a)*s)/d = P/d, f'' = (1-a)*e/d^2
//   f~ = a*x + (1-a)*(log(d) + max(x,0)) - y
//   Halley: x -= 2*f~*P*d / (2*P^2 - f~*(1-a)*e)
// => 3 MUFU ops/iter (EX2, LG2, RCP). 9 MUFU/elem vs 24 in the Newton version.
// Worst-case convergence (y~0-, init err 1.4): 1.4 -> ~0.09 -> ~1e-4 -> ~1e-12.

#define HALLEY_ITERS 3

__device__ __forceinline__ float rcp_approx(float x) {
    float r;
    asm("rcp.approx.ftz.f32 %0, %1;" : "=f"(r) : "f"(x));
    return r;
}

__device__ __forceinline__ float halley_solve(float y, float a, float oma, float inv_a) {
    float x = (y > 0.0f) ? y : y * inv_a;
#pragma unroll
    for (int it = 0; it < HALLEY_ITERS; ++it) {
        float e  = __expf(-fabsf(x));            // MUFU EX2
        float d  = 1.0f + e;
        float l  = __logf(d);                    // MUFU LG2 (= log1p(e), d in [1,2])
        float sp = l + fmaxf(x, 0.0f);           // softplus(x)
        float ft = fmaf(oma, sp, fmaf(a, x, -y));// f(x) - y
        float s  = (x > 0.0f) ? 1.0f : e;        // sigma numerator
        float P  = fmaf(a, d, oma * s);          // d * f'(x)
        float oe = oma * e;                      // d^2 * f''(x)
        float num = (ft + ft) * (P * d);         // 2*f~*P*d
        float den = fmaf(P + P, P, -ft * oe);    // 2*P^2 - f~*(1-a)*e  (> 0 always)
        x = fmaf(-num, rcp_approx(den), x);      // MUFU RCP
    }
    return x;
}

__global__ __launch_bounds__(256)
void inv_leaky_softplus_kernel(const float4* __restrict__ in,
                               const float* __restrict__ raw_alpha,
                               float4* __restrict__ out,
                               int n4, int n_rem,
                               const float* __restrict__ rem_in,
                               float* __restrict__ rem_out) {
    // alpha is a broadcast scalar; per-thread recompute is negligible
    float ra    = raw_alpha[0];
    float a     = fmaf(0.4f, rcp_approx(1.0f + __expf(-ra)), 0.1f);
    float oma   = 1.0f - a;
    float inv_a = rcp_approx(a);
    inv_a = inv_a * (2.0f - a * inv_a);          // refine to full precision

    int i = blockIdx.x * blockDim.x + threadIdx.x;
    if (i < n4) {
        float4 y4 = in[i];
        float4 x4;
        x4.x = halley_solve(y4.x, a, oma, inv_a);
        x4.y = halley_solve(y4.y, a, oma, inv_a);
        x4.z = halley_solve(y4.z, a, oma, inv_a);
        x4.w = halley_solve(y4.w, a, oma, inv_a);
        out[i] = x4;
    }
    if (i < n_rem) {
        rem_out[i] = halley_solve(rem_in[i], a, oma, inv_a);
    }
}

extern "C" void kernel_launch(void* const* d_in, const int* in_sizes, int n_in,
                              void* d_out, int out_size) {
    const float* inp   = (const float*)d_in[0];
    const float* alpha = (const float*)d_in[1];
    float*       outp  = (float*)d_out;

    int n     = in_sizes[0];
    int n4    = n >> 2;
    int n_rem = n & 3;
    const float* rem_in  = inp  + (size_t)n4 * 4;
    float*       rem_out = outp + (size_t)n4 * 4;

    int threads = 256;
    int work    = (n4 > n_rem) ? n4 : n_rem;
    int blocks  = (work + threads - 1) / threads;
    if (blocks < 1) blocks = 1;

    inv_leaky_softplus_kernel<<<blocks, threads>>>(
        (const float4*)inp, alpha, (float4*)outp, n4, n_rem, rem_in, rem_out);
}

// round 3
// speedup vs baseline: 2.3319x; 1.3865x over previous
#include <cuda_runtime.h>
#include <cuda_bf16.h>

// Inverse of f(x) = a*x + (1-a)*softplus(x), a = 0.1 + 0.4*sigmoid(raw_alpha).
//
// R3: 2 Halley iterations with shifted init.
//   Identity: f(x) = x + (1-a)*softplus(-x)  =>  exact correction at x=0 is
//   c = (1-a)*ln2. Init x0 = sel(y>0, y, y/a) - c has worst-case error 0.79
//   (at y~0) instead of 1.39; two Halley steps contract it 0.79 -> 0.012 -> 5e-5.
//   Large |y|: function is locally linear, converges in one step.
//
// Per iteration (3 MUFU: EX2, LG2, RCP):
//   e = exp(-|x|), d = 1+e, sp = ln2*log2(d) + max(x,0)
//   ft = a*x + (1-a)*sp - y
//   s = (x>0 ? 1 : e);  P = d*f' = a*d + (1-a)*s
//   Halley (halved):  x -= ft*P*d / (P^2 - 0.5*ft*(1-a)*e)

#define HALLEY_ITERS 2
#define LN2F  0.6931471805599453f

__device__ __forceinline__ float rcp_approx(float x) {
    float r;
    asm("rcp.approx.ftz.f32 %0, %1;" : "=f"(r) : "f"(x));
    return r;
}

__device__ __forceinline__ float lg2_approx(float x) {
    float r;
    asm("lg2.approx.ftz.f32 %0, %1;" : "=f"(r) : "f"(x));
    return r;
}

__device__ __forceinline__ float halley_solve(float y, float a, float oma,
                                              float omah, float inv_a, float c) {
    float x = ((y > 0.0f) ? y : y * inv_a) - c;
#pragma unroll
    for (int it = 0; it < HALLEY_ITERS; ++it) {
        float e   = __expf(-fabsf(x));              // MUFU EX2 (+1 mul)
        float d   = 1.0f + e;
        float l2  = lg2_approx(d);                  // MUFU LG2
        float sp  = fmaf(LN2F, l2, fmaxf(x, 0.0f)); // softplus(x)
        float ft  = fmaf(oma, sp, fmaf(a, x, -y));  // f(x) - y
        float s   = (x > 0.0f) ? 1.0f : e;
        float P   = fmaf(a, d, oma * s);            // d * f'(x)
        float num = ft * (P * d);
        float den = fmaf(P, P, -(ft * (omah * e))); // P^2 - ft*(1-a)*e/2  (>0)
        x = fmaf(-num, rcp_approx(den), x);         // MUFU RCP
    }
    return x;
}

__global__ __launch_bounds__(256)
void inv_leaky_softplus_kernel(const float4* __restrict__ in,
                               const float* __restrict__ raw_alpha,
                               float4* __restrict__ out,
                               int n4, int n_rem,
                               const float* __restrict__ rem_in,
                               float* __restrict__ rem_out) {
    float ra    = raw_alpha[0];
    float a     = fmaf(0.4f, rcp_approx(1.0f + __expf(-ra)), 0.1f);
    float oma   = 1.0f - a;
    float omah  = 0.5f * oma;
    float c     = oma * LN2F;
    float inv_a = rcp_approx(a);
    inv_a = inv_a * (2.0f - a * inv_a);             // refine to full precision

    int i = blockIdx.x * blockDim.x + threadIdx.x;
    if (i < n4) {
        float4 y4 = in[i];
        float4 x4;
        x4.x = halley_solve(y4.x, a, oma, omah, inv_a, c);
        x4.y = halley_solve(y4.y, a, oma, omah, inv_a, c);
        x4.z = halley_solve(y4.z, a, oma, omah, inv_a, c);
        x4.w = halley_solve(y4.w, a, oma, omah, inv_a, c);
        out[i] = x4;
    }
    if (i < n_rem) {
        rem_out[i] = halley_solve(rem_in[i], a, oma, omah, inv_a, c);
    }
}

extern "C" void kernel_launch(void* const* d_in, const int* in_sizes, int n_in,
                              void* d_out, int out_size) {
    const float* inp   = (const float*)d_in[0];
    const float* alpha = (const float*)d_in[1];
    float*       outp  = (float*)d_out;

    int n     = in_sizes[0];
    int n4    = n >> 2;
    int n_rem = n & 3;
    const float* rem_in  = inp  + (size_t)n4 * 4;
    float*       rem_out = outp + (size_t)n4 * 4;

    int threads = 256;
    int work    = (n4 > n_rem) ? n4 : n_rem;
    int blocks  = (work + threads - 1) / threads;
    if (blocks < 1) blocks = 1;

    inv_leaky_softplus_kernel<<<blocks, threads>>>(
        (const float4*)inp, alpha, (float4*)outp, n4, n_rem, rem_in, rem_out);
}

// round 4
// speedup vs baseline: 2.7328x; 1.1719x over previous
#include <cuda_runtime.h>
#include <cuda_bf16.h>

// Inverse of f(x) = a*x + (1-a)*softplus(x), a = 0.1 + 0.4*sigmoid(raw_alpha).
//
// R4: 2 Halley iterations, FMA-pipe work packed as f32x2 over lane pairs
// (Blackwell FFMA2/FMUL2/FADD2 — only reachable via PTX fma.rn.f32x2 etc.).
// MUFU (EX2/LG2/RCP), FSEL, FMNMX stay scalar. Signs are arranged so that no
// packed negation is needed: G = -(f(x)-y) = y - a*x - (1-a)*sp, and
//   den = P^2 - ft*omah*e = fma2(P, P, G*(omah*e))
//   x  += G*P*d * rcp(den)
//
// 3 MUFU / elem / iter (EX2, LG2, RCP) -> 6 MUFU/elem total.

#define LN2F   0.6931471805599453f
#define L2EF   1.4426950408889634f

typedef unsigned long long ull;

__device__ __forceinline__ ull pack2(float lo, float hi) {
    ull r; asm("mov.b64 %0, {%1, %2};" : "=l"(r) : "f"(lo), "f"(hi)); return r;
}
__device__ __forceinline__ void unpack2(ull v, float& lo, float& hi) {
    asm("mov.b64 {%0, %1}, %2;" : "=f"(lo), "=f"(hi) : "l"(v));
}
__device__ __forceinline__ ull fma2(ull a, ull b, ull c) {
    ull d; asm("fma.rn.f32x2 %0, %1, %2, %3;" : "=l"(d) : "l"(a), "l"(b), "l"(c)); return d;
}
__device__ __forceinline__ ull mul2(ull a, ull b) {
    ull d; asm("mul.rn.f32x2 %0, %1, %2;" : "=l"(d) : "l"(a), "l"(b)); return d;
}
__device__ __forceinline__ ull add2(ull a, ull b) {
    ull d; asm("add.rn.f32x2 %0, %1, %2;" : "=l"(d) : "l"(a), "l"(b)); return d;
}
__device__ __forceinline__ float rcp_approx(float x) {
    float r; asm("rcp.approx.ftz.f32 %0, %1;" : "=f"(r) : "f"(x)); return r;
}
__device__ __forceinline__ float lg2_approx(float x) {
    float r; asm("lg2.approx.ftz.f32 %0, %1;" : "=f"(r) : "f"(x)); return r;
}
__device__ __forceinline__ float ex2_approx(float x) {
    float r; asm("ex2.approx.ftz.f32 %0, %1;" : "=f"(r) : "f"(x)); return r;
}

struct Consts {
    ull k2;      // splat(inv_a - 1)
    ull negc2;   // splat(-(1-a)*ln2)
    ull one2;    // splat(1.0)
    ull ln2_2;   // splat(ln2)
    ull a2;      // splat(a)
    ull na2;     // splat(-a)
    ull oma2;    // splat(1-a)
    ull noma2;   // splat(-(1-a))
    ull omah2;   // splat(0.5*(1-a))
    float a;     // scalar copies for the tail path
    float oma, omah, inv_a, c;
};

// Packed Halley solve for a lane pair packed in Y.
__device__ __forceinline__ ull halley_pair(ull Y, const Consts& C) {
    float y0, y1; unpack2(Y, y0, y1);
    // x0 = y + min(y,0)*(1/a - 1) - c   (== sel(y>0, y, y/a) - c)
    ull M = pack2(fminf(y0, 0.0f), fminf(y1, 0.0f));
    ull X = fma2(M, C.k2, add2(Y, C.negc2));
#pragma unroll
    for (int it = 0; it < 2; ++it) {
        float x0, x1; unpack2(X, x0, x1);
        float e0 = ex2_approx(-fabsf(x0) * L2EF);        // FMUL(|.|,-) + MUFU
        float e1 = ex2_approx(-fabsf(x1) * L2EF);
        ull  E  = pack2(e0, e1);
        ull  D  = add2(E, C.one2);                       // d = 1+e
        float d0, d1; unpack2(D, d0, d1);
        float l0 = lg2_approx(d0);                       // MUFU LG2
        float l1 = lg2_approx(d1);
        ull  SP = fma2(pack2(l0, l1), C.ln2_2,
                       pack2(fmaxf(x0, 0.0f), fmaxf(x1, 0.0f)));  // softplus
        ull  G  = fma2(C.noma2, SP, fma2(C.na2, X, Y));  // y - f(x)  (= -ft)
        ull  S  = pack2((x0 > 0.0f) ? 1.0f : e0,
                        (x1 > 0.0f) ? 1.0f : e1);
        ull  P  = fma2(C.a2, D, mul2(C.oma2, S));        // d * f'(x)
        ull  DEN = fma2(P, P, mul2(G, mul2(C.omah2, E)));// P^2 - ft*(1-a)e/2 > 0
        float dn0, dn1; unpack2(DEN, dn0, dn1);
        ull  R  = pack2(rcp_approx(dn0), rcp_approx(dn1)); // MUFU RCP
        ull  GPD = mul2(G, mul2(P, D));                  // -ft*P*d
        X = fma2(GPD, R, X);                             // x += G*P*d/den
    }
    return X;
}

// Scalar fallback for tail elements.
__device__ __forceinline__ float halley_scalar(float y, const Consts& C) {
    float x = ((y > 0.0f) ? y : y * C.inv_a) - C.c;
#pragma unroll
    for (int it = 0; it < 2; ++it) {
        float e  = ex2_approx(-fabsf(x) * L2EF);
        float d  = 1.0f + e;
        float sp = fmaf(LN2F, lg2_approx(d), fmaxf(x, 0.0f));
        float g  = fmaf(-C.oma, sp, fmaf(-C.a, x, y));
        float s  = (x > 0.0f) ? 1.0f : e;
        float P  = fmaf(C.a, d, C.oma * s);
        float den = fmaf(P, P, g * (C.omah * e));
        x = fmaf(g * (P * d), rcp_approx(den), x);
    }
    return x;
}

__global__ __launch_bounds__(256)
void inv_leaky_softplus_kernel(const float4* __restrict__ in,
                               const float* __restrict__ raw_alpha,
                               float4* __restrict__ out,
                               int n4, int n_rem,
                               const float* __restrict__ rem_in,
                               float* __restrict__ rem_out) {
    float ra  = raw_alpha[0];
    float a   = fmaf(0.4f, rcp_approx(1.0f + ex2_approx(-ra * L2EF)), 0.1f);
    float oma = 1.0f - a;
    float iva = rcp_approx(a);
    iva = iva * (2.0f - a * iva);    // refine reciprocal to full precision

    Consts C;
    C.a = a; C.oma = oma; C.omah = 0.5f * oma; C.inv_a = iva; C.c = oma * LN2F;
    C.k2    = pack2(iva - 1.0f, iva - 1.0f);
    C.negc2 = pack2(-C.c, -C.c);
    C.one2  = pack2(1.0f, 1.0f);
    C.ln2_2 = pack2(LN2F, LN2F);
    C.a2    = pack2(a, a);
    C.na2   = pack2(-a, -a);
    C.oma2  = pack2(oma, oma);
    C.noma2 = pack2(-oma, -oma);
    C.omah2 = pack2(C.omah, C.omah);

    int i = blockIdx.x * blockDim.x + threadIdx.x;
    if (i < n4) {
        float4 y4 = in[i];
        ull Y01 = pack2(y4.x, y4.y);
        ull Y23 = pack2(y4.z, y4.w);
        ull X01 = halley_pair(Y01, C);
        ull X23 = halley_pair(Y23, C);
        float4 x4;
        unpack2(X01, x4.x, x4.y);
        unpack2(X23, x4.z, x4.w);
        out[i] = x4;
    }
    if (i < n_rem) {
        rem_out[i] = halley_scalar(rem_in[i], C);
    }
}

extern "C" void kernel_launch(void* const* d_in, const int* in_sizes, int n_in,
                              void* d_out, int out_size) {
    const float* inp   = (const float*)d_in[0];
    const float* alpha = (const float*)d_in[1];
    float*       outp  = (float*)d_out;

    int n     = in_sizes[0];
    int n4    = n >> 2;
    int n_rem = n & 3;
    const float* rem_in  = inp  + (size_t)n4 * 4;
    float*       rem_out = outp + (size_t)n4 * 4;

    int threads = 256;
    int work    = (n4 > n_rem) ? n4 : n_rem;
    int blocks  = (work + threads - 1) / threads;
    if (blocks < 1) blocks = 1;

    inv_leaky_softplus_kernel<<<blocks, threads>>>(
        (const float4*)inp, alpha, (float4*)outp, n4, n_rem, rem_in, rem_out);
}